// round 1
// baseline (speedup 1.0000x reference)
#include <cuda_runtime.h>

#define BB 4
#define LL 256
#define DD 256

// scratch (allocation-free contract: __device__ globals)
__device__ float g_S[BB * LL * DD];   // 1 MB
__device__ float g_A[BB * LL];
__device__ float g_Wt[DD * DD];       // W transposed: Wt[d*256 + o]

// ---------------------------------------------------------------------------
// kT: transpose W[o,d] -> Wt[d,o]  (256x256, tiled, conflict-free)
// ---------------------------------------------------------------------------
__global__ void __launch_bounds__(256) kT(const float* __restrict__ W) {
    __shared__ float tile[32][33];
    int tx = threadIdx.x, ty = threadIdx.y;           // block (32, 8)
    int d0 = blockIdx.x * 32, o0 = blockIdx.y * 32;
#pragma unroll
    for (int k = 0; k < 32; k += 8)
        tile[ty + k][tx] = W[(o0 + ty + k) * DD + (d0 + tx)];
    __syncthreads();
#pragma unroll
    for (int k = 0; k < 32; k += 8)
        g_Wt[(d0 + ty + k) * DD + (o0 + tx)] = tile[tx][ty + k];
}

// ---------------------------------------------------------------------------
// k_dep: S[b,i,d] = sum_j adj[b,i,j] * (text[b,j,d] + dep[b,j,i,d])
//        A[b,i]   = sum_j adj[b,i,j]
// grid = B * L/4 = 256 blocks; block = 256 threads.
// thread t: jj = t>>6 owns j in [jj*64, jj*64+64); d4 = t&63 owns float4 lane.
// Each block covers 4 consecutive i so each text row is read once per 4 dep rows.
// ---------------------------------------------------------------------------
__global__ void __launch_bounds__(256) k_dep(const float* __restrict__ text,
                                             const float* __restrict__ adj,
                                             const float* __restrict__ dep) {
    const int bx = blockIdx.x;
    const int b  = bx >> 6;
    const int i0 = (bx & 63) << 2;
    const int t  = threadIdx.x;
    const int jj = t >> 6;
    const int d4 = t & 63;

    __shared__ float  adjs[4][LL];
    __shared__ float4 red[16][64];   // [jj*4 + i][d4]

    // stage the 4 adj rows
    const float* adjb = adj + (b * LL + i0) * LL;
#pragma unroll
    for (int i = 0; i < 4; i++) adjs[i][t] = adjb[i * LL + t];
    __syncthreads();

    // A[b, i0+w] row-sums (warps 0..3), overlapped with main loop issue
    {
        const int warp = t >> 5, lane = t & 31;
        if (warp < 4) {
            float s = 0.f;
#pragma unroll
            for (int k = 0; k < 8; k++) s += adjs[warp][lane + 32 * k];
#pragma unroll
            for (int off = 16; off; off >>= 1)
                s += __shfl_xor_sync(0xffffffffu, s, off);
            if (lane == 0) g_A[b * LL + i0 + warp] = s;
        }
    }

    const float4* text4 = (const float4*)text + (size_t)b * LL * 64;
    // dep element (j, i0+i, d4) -> dep4[(j*LL + i)*64 + d4]
    const float4* dep4 = (const float4*)dep + ((size_t)(b * LL) * LL + i0) * 64;

    float4 acc[4];
#pragma unroll
    for (int i = 0; i < 4; i++) acc[i] = make_float4(0.f, 0.f, 0.f, 0.f);

    const int jbase = jj << 6;
#pragma unroll 2
    for (int js = 0; js < 64; js += 2) {
        const int j0 = jbase + js;
        float4 tx[2], dv[2][4];
        // batch 10 independent LDG.128 for MLP
#pragma unroll
        for (int u = 0; u < 2; u++) {
            tx[u] = text4[(j0 + u) * 64 + d4];
#pragma unroll
            for (int i = 0; i < 4; i++)
                dv[u][i] = dep4[((j0 + u) * LL + i) * 64 + d4];
        }
#pragma unroll
        for (int u = 0; u < 2; u++) {
            const int j = j0 + u;
#pragma unroll
            for (int i = 0; i < 4; i++) {
                const float a = adjs[i][j];
                acc[i].x += a * (tx[u].x + dv[u][i].x);
                acc[i].y += a * (tx[u].y + dv[u][i].y);
                acc[i].z += a * (tx[u].z + dv[u][i].z);
                acc[i].w += a * (tx[u].w + dv[u][i].w);
            }
        }
    }

    // reduce the 4 jj-partials per (i, d4)
#pragma unroll
    for (int i = 0; i < 4; i++) red[jj * 4 + i][d4] = acc[i];
    __syncthreads();
    {
        const int io = t >> 6, dd = t & 63;
        float4 r0 = red[0 + io][dd];
        float4 r1 = red[4 + io][dd];
        float4 r2 = red[8 + io][dd];
        float4 r3 = red[12 + io][dd];
        float4 s;
        s.x = (r0.x + r1.x) + (r2.x + r3.x);
        s.y = (r0.y + r1.y) + (r2.y + r3.y);
        s.z = (r0.z + r1.z) + (r2.z + r3.z);
        s.w = (r0.w + r1.w) + (r2.w + r3.w);
        ((float4*)g_S)[(b * LL + i0 + io) * 64 + dd] = s;
    }
}

// ---------------------------------------------------------------------------
// k_out: out[row,o] = sum_d S[row,d] * Wt[d,o] + A[row]*bias[o]
// grid = 1024/8 = 128 blocks; block = 256 threads.
// thread: o4 = t&63 (float4 of o), rg = t>>6 -> rows rg*2, rg*2+1
// ---------------------------------------------------------------------------
__global__ void __launch_bounds__(256) k_out(const float* __restrict__ bias,
                                             float* __restrict__ out) {
    const int row0 = blockIdx.x * 8;
    const int t  = threadIdx.x;
    const int o4 = t & 63;
    const int rg = t >> 6;

    __shared__ float Ssm[8][DD];
    __shared__ float Asm[8];

    const float4* Sg  = (const float4*)(g_S + row0 * DD);
    float4*       Ss4 = (float4*)&Ssm[0][0];
    Ss4[t]       = Sg[t];
    Ss4[t + 256] = Sg[t + 256];
    if (t < 8) Asm[t] = g_A[row0 + t];
    __syncthreads();

    const int r0 = rg * 2, r1 = rg * 2 + 1;
    float4 acc0 = make_float4(0.f, 0.f, 0.f, 0.f);
    float4 acc1 = make_float4(0.f, 0.f, 0.f, 0.f);
    const float4* Wt4 = (const float4*)g_Wt;

#pragma unroll 4
    for (int d = 0; d < DD; d++) {
        const float4 w = Wt4[d * 64 + o4];
        const float s0 = Ssm[r0][d];
        const float s1 = Ssm[r1][d];
        acc0.x += s0 * w.x;  acc0.y += s0 * w.y;
        acc0.z += s0 * w.z;  acc0.w += s0 * w.w;
        acc1.x += s1 * w.x;  acc1.y += s1 * w.y;
        acc1.z += s1 * w.z;  acc1.w += s1 * w.w;
    }

    const float4 bi = ((const float4*)bias)[o4];
    const float a0 = Asm[r0], a1 = Asm[r1];
    acc0.x += a0 * bi.x;  acc0.y += a0 * bi.y;
    acc0.z += a0 * bi.z;  acc0.w += a0 * bi.w;
    acc1.x += a1 * bi.x;  acc1.y += a1 * bi.y;
    acc1.z += a1 * bi.z;  acc1.w += a1 * bi.w;

    ((float4*)(out + (row0 + r0) * DD))[o4] = acc0;
    ((float4*)(out + (row0 + r1) * DD))[o4] = acc1;
}

// ---------------------------------------------------------------------------
extern "C" void kernel_launch(void* const* d_in, const int* in_sizes, int n_in,
                              void* d_out, int out_size) {
    const float* text = (const float*)d_in[0];  // [4,256,256]
    const float* adj  = (const float*)d_in[1];  // [4,256,256]
    const float* dep  = (const float*)d_in[2];  // [4,256,256,256]
    const float* W    = (const float*)d_in[3];  // [256,256]
    const float* bias = (const float*)d_in[4];  // [256]
    float* out = (float*)d_out;                 // [4,256,256]

    kT<<<dim3(8, 8), dim3(32, 8)>>>(W);
    k_dep<<<BB * LL / 4, 256>>>(text, adj, dep);
    k_out<<<BB * LL / 8, 256>>>(bias, out);
}

// round 2
// speedup vs baseline: 1.0837x; 1.0837x over previous
#include <cuda_runtime.h>

#define BB 4
#define LL 256
#define DD 256

// scratch (allocation-free contract: __device__ globals)
__device__ float g_Sdep[BB * LL * DD];  // 1 MB : sum_j adj * dep
__device__ float g_S0[BB * LL * DD];    // 1 MB : adj @ text
__device__ float g_A[BB * LL];          // row sums of adj
__device__ float g_Wt[DD * DD];         // W transposed: Wt[d*256 + o]

// ---------------------------------------------------------------------------
// k_dep: Sdep[b,i,d] = sum_j adj[b,i,j] * dep[b,j,i,d]
// grid = B*L = 1024 blocks (one (b,i) each); block = 256 threads.
// thread t: jj = t>>6 owns 64 j's; d4 = t&63 owns one float4 lane of d.
// dep rows (1KB each) are perfectly coalesced; __ldcs since zero reuse.
// ---------------------------------------------------------------------------
__global__ void __launch_bounds__(256) k_dep(const float* __restrict__ adj,
                                             const float* __restrict__ dep) {
    const int bx = blockIdx.x;
    const int b  = bx >> 8;
    const int i  = bx & 255;
    const int t  = threadIdx.x;
    const int jj = t >> 6;
    const int d4 = t & 63;

    __shared__ float  adjs[LL];
    __shared__ float4 red[4][64];

    adjs[t] = adj[(b * LL + i) * LL + t];
    __syncthreads();

    // dep element (b, j, i, d4-lane) as float4:
    const int jbase = jj << 6;
    const float4* p = (const float4*)dep
                    + (((size_t)(b * LL + jbase) * LL + i) << 6) + d4;
    const size_t jstride = (size_t)LL << 6;   // 16384 float4 per j

    float4 acc = make_float4(0.f, 0.f, 0.f, 0.f);

#pragma unroll 1
    for (int js = 0; js < 64; js += 8) {
        float4 dv[8];
#pragma unroll
        for (int u = 0; u < 8; u++)
            dv[u] = __ldcs(p + (size_t)u * jstride);   // 8 independent LDG.128
        p += jstride * 8;
#pragma unroll
        for (int u = 0; u < 8; u++) {
            const float a = adjs[jbase + js + u];
            acc.x += a * dv[u].x;
            acc.y += a * dv[u].y;
            acc.z += a * dv[u].z;
            acc.w += a * dv[u].w;
        }
    }

    red[jj][d4] = acc;
    __syncthreads();
    if (t < 64) {
        float4 r0 = red[0][t], r1 = red[1][t], r2 = red[2][t], r3 = red[3][t];
        float4 s;
        s.x = (r0.x + r1.x) + (r2.x + r3.x);
        s.y = (r0.y + r1.y) + (r2.y + r3.y);
        s.z = (r0.z + r1.z) + (r2.z + r3.z);
        s.w = (r0.w + r1.w) + (r2.w + r3.w);
        ((float4*)g_Sdep)[((b * LL + i) << 6) + t] = s;
    }
}

// ---------------------------------------------------------------------------
// k_pre: blocks [0,128)  : S0[row,d] = sum_j adj[row,j]*text[b,j,d]; A[row]
//        blocks [128,192): W transpose -> g_Wt
// block = 256 threads. All inputs L2-resident (adj 1MB, text 1MB, W 256KB).
// ---------------------------------------------------------------------------
__global__ void __launch_bounds__(256) k_pre(const float* __restrict__ adj,
                                             const float* __restrict__ text,
                                             const float* __restrict__ W) {
    const int t = threadIdx.x;

    if (blockIdx.x >= 128) {
        // ---- W transpose: 64 blocks of 32x32 tiles ----
        __shared__ float tile[32][33];
        const int bb = blockIdx.x - 128;
        const int d0 = (bb & 7) * 32, o0 = (bb >> 3) * 32;
        const int tx = t & 31, ty = t >> 5;   // (32, 8)
#pragma unroll
        for (int k = 0; k < 32; k += 8)
            tile[ty + k][tx] = W[(o0 + ty + k) * DD + (d0 + tx)];
        __syncthreads();
#pragma unroll
        for (int k = 0; k < 32; k += 8)
            g_Wt[(d0 + ty + k) * DD + (o0 + tx)] = tile[tx][ty + k];
        return;
    }

    // ---- GEMM rows: 8 (b,i) rows per block ----
    const int row0 = blockIdx.x * 8;          // global row = b*256 + i
    const int b    = row0 >> 8;

    __shared__ float adjs[8][LL];

    const float* adjg = adj + (size_t)row0 * LL;
#pragma unroll
    for (int r = 0; r < 8; r++) adjs[r][t] = adjg[r * LL + t];
    __syncthreads();

    // A row sums: warp w reduces adjs[w]
    {
        const int warp = t >> 5, lane = t & 31;
        float s = 0.f;
#pragma unroll
        for (int k = 0; k < 8; k++) s += adjs[warp][lane + 32 * k];
#pragma unroll
        for (int off = 16; off; off >>= 1)
            s += __shfl_xor_sync(0xffffffffu, s, off);
        if (lane == 0) g_A[row0 + warp] = s;
    }

    const int o4 = t & 63;       // float4 lane of d
    const int rg = t >> 6;       // owns rows rg*2, rg*2+1
    const int r0 = rg * 2, r1 = r0 + 1;

    const float4* text4 = (const float4*)text + ((size_t)b * LL << 6) + o4;
    float4 acc0 = make_float4(0.f, 0.f, 0.f, 0.f);
    float4 acc1 = make_float4(0.f, 0.f, 0.f, 0.f);

#pragma unroll 4
    for (int j = 0; j < LL; j++) {
        const float4 tv = text4[j << 6];
        const float a0 = adjs[r0][j];
        const float a1 = adjs[r1][j];
        acc0.x += a0 * tv.x;  acc0.y += a0 * tv.y;
        acc0.z += a0 * tv.z;  acc0.w += a0 * tv.w;
        acc1.x += a1 * tv.x;  acc1.y += a1 * tv.y;
        acc1.z += a1 * tv.z;  acc1.w += a1 * tv.w;
    }

    ((float4*)g_S0)[((row0 + r0) << 6) + o4] = acc0;
    ((float4*)g_S0)[((row0 + r1) << 6) + o4] = acc1;
}

// ---------------------------------------------------------------------------
// k_out: out[row,o] = sum_d (S0+Sdep)[row,d] * Wt[d,o] + A[row]*bias[o]
// grid = 128 blocks of 8 rows; block = 256 threads.
// ---------------------------------------------------------------------------
__global__ void __launch_bounds__(256) k_out(const float* __restrict__ bias,
                                             float* __restrict__ out) {
    const int row0 = blockIdx.x * 8;
    const int t  = threadIdx.x;
    const int o4 = t & 63;
    const int rg = t >> 6;

    __shared__ float Ssm[8][DD];
    __shared__ float Asm[8];

    const float4* S0g = (const float4*)(g_S0   + (size_t)row0 * DD);
    const float4* Sdg = (const float4*)(g_Sdep + (size_t)row0 * DD);
    float4* Ss4 = (float4*)&Ssm[0][0];
#pragma unroll
    for (int k = 0; k < 2; k++) {
        float4 a = S0g[t + 256 * k];
        float4 c = Sdg[t + 256 * k];
        a.x += c.x; a.y += c.y; a.z += c.z; a.w += c.w;
        Ss4[t + 256 * k] = a;
    }
    if (t < 8) Asm[t] = g_A[row0 + t];
    __syncthreads();

    const int r0 = rg * 2, r1 = rg * 2 + 1;
    float4 acc0 = make_float4(0.f, 0.f, 0.f, 0.f);
    float4 acc1 = make_float4(0.f, 0.f, 0.f, 0.f);
    const float4* Wt4 = (const float4*)g_Wt + o4;

#pragma unroll 4
    for (int d = 0; d < DD; d++) {
        const float4 w = Wt4[d << 6];
        const float s0 = Ssm[r0][d];
        const float s1 = Ssm[r1][d];
        acc0.x += s0 * w.x;  acc0.y += s0 * w.y;
        acc0.z += s0 * w.z;  acc0.w += s0 * w.w;
        acc1.x += s1 * w.x;  acc1.y += s1 * w.y;
        acc1.z += s1 * w.z;  acc1.w += s1 * w.w;
    }

    const float4 bi = ((const float4*)bias)[o4];
    const float a0 = Asm[r0], a1 = Asm[r1];
    acc0.x += a0 * bi.x;  acc0.y += a0 * bi.y;
    acc0.z += a0 * bi.z;  acc0.w += a0 * bi.w;
    acc1.x += a1 * bi.x;  acc1.y += a1 * bi.y;
    acc1.z += a1 * bi.z;  acc1.w += a1 * bi.w;

    ((float4*)(out + (size_t)(row0 + r0) * DD))[o4] = acc0;
    ((float4*)(out + (size_t)(row0 + r1) * DD))[o4] = acc1;
}

// ---------------------------------------------------------------------------
extern "C" void kernel_launch(void* const* d_in, const int* in_sizes, int n_in,
                              void* d_out, int out_size) {
    const float* text = (const float*)d_in[0];  // [4,256,256]
    const float* adj  = (const float*)d_in[1];  // [4,256,256]
    const float* dep  = (const float*)d_in[2];  // [4,256,256,256]
    const float* W    = (const float*)d_in[3];  // [256,256]
    const float* bias = (const float*)d_in[4];  // [256]
    float* out = (float*)d_out;                 // [4,256,256]

    // order chosen so the ncu-profiled slot lands on k_dep
    k_dep<<<BB * LL, 256>>>(adj, dep);
    k_pre<<<192, 256>>>(adj, text, W);
    k_out<<<BB * LL / 8, 256>>>(bias, out);
}

// round 3
// speedup vs baseline: 1.4355x; 1.3246x over previous
#include <cuda_runtime.h>

#define BB 4
#define LL 256
#define DD 256

// scratch (allocation-free contract: __device__ globals)
__device__ float g_Sdep[BB * LL * DD];  // 1 MB : sum_j adj * dep
__device__ float g_S0[BB * LL * DD];    // 1 MB : adj @ text
__device__ float g_A[BB * LL];          // row sums of adj
__device__ float g_Wt[DD * DD];         // W transposed: Wt[d*256 + o]

// ---------------------------------------------------------------------------
// k_fused: one grid, three block roles.
//   bx in [0,128)    : S0[row,d] = sum_j adj[row,j]*text[b,j,d]; A[row]
//   bx in [128,192)  : W transpose -> g_Wt
//   bx in [192,1216) : Sdep[b,i,d] = sum_j adj[b,i,j]*dep[b,j,i,d]  (DRAM stream)
// GEMM/transpose blocks are first so they schedule in wave 1 and finish early;
// their L2/FMA work hides entirely under the DRAM-bound dep stream.
// ---------------------------------------------------------------------------
__global__ void __launch_bounds__(256) k_fused(const float* __restrict__ text,
                                               const float* __restrict__ adj,
                                               const float* __restrict__ dep,
                                               const float* __restrict__ W) {
    const int bx = blockIdx.x;
    const int t  = threadIdx.x;

    if (bx < 128) {
        // ---- S0 = adj @ text (8 rows per block), plus A row sums ----
        __shared__ float adjs[8][LL];
        const int row0 = bx * 8;            // global row = b*256 + i
        const int b    = row0 >> 8;

        const float* adjg = adj + (size_t)row0 * LL;
#pragma unroll
        for (int r = 0; r < 8; r++) adjs[r][t] = adjg[r * LL + t];
        __syncthreads();

        {   // A row sums: warp w reduces adjs[w]
            const int warp = t >> 5, lane = t & 31;
            float s = 0.f;
#pragma unroll
            for (int k = 0; k < 8; k++) s += adjs[warp][lane + 32 * k];
#pragma unroll
            for (int off = 16; off; off >>= 1)
                s += __shfl_xor_sync(0xffffffffu, s, off);
            if (lane == 0) g_A[row0 + warp] = s;
        }

        const int o4 = t & 63;
        const int rg = t >> 6;
        const int r0 = rg * 2, r1 = r0 + 1;

        const float4* text4 = (const float4*)text + ((size_t)b * LL << 6) + o4;
        float4 acc0 = make_float4(0.f, 0.f, 0.f, 0.f);
        float4 acc1 = make_float4(0.f, 0.f, 0.f, 0.f);

#pragma unroll 1
        for (int j = 0; j < LL; j += 4) {
            float4 tv[4];
#pragma unroll
            for (int u = 0; u < 4; u++) tv[u] = text4[(j + u) << 6];
#pragma unroll
            for (int u = 0; u < 4; u++) {
                const float a0 = adjs[r0][j + u];
                const float a1 = adjs[r1][j + u];
                acc0.x += a0 * tv[u].x;  acc0.y += a0 * tv[u].y;
                acc0.z += a0 * tv[u].z;  acc0.w += a0 * tv[u].w;
                acc1.x += a1 * tv[u].x;  acc1.y += a1 * tv[u].y;
                acc1.z += a1 * tv[u].z;  acc1.w += a1 * tv[u].w;
            }
        }
        ((float4*)g_S0)[((row0 + r0) << 6) + o4] = acc0;
        ((float4*)g_S0)[((row0 + r1) << 6) + o4] = acc1;
        return;
    }

    if (bx < 192) {
        // ---- W transpose: 64 blocks of 32x32 tiles ----
        __shared__ float tile[32][33];
        const int bb = bx - 128;
        const int d0 = (bb & 7) * 32, o0 = (bb >> 3) * 32;
        const int tx = t & 31, ty = t >> 5;   // (32, 8)
#pragma unroll
        for (int k = 0; k < 32; k += 8)
            tile[ty + k][tx] = W[(o0 + ty + k) * DD + (d0 + tx)];
        __syncthreads();
#pragma unroll
        for (int k = 0; k < 32; k += 8)
            g_Wt[(d0 + ty + k) * DD + (o0 + tx)] = tile[tx][ty + k];
        return;
    }

    // ---- dep stream: one (b,i) per block ----
    {
        const int id = bx - 192;
        const int b  = id >> 8;
        const int i  = id & 255;
        const int jj = t >> 6;
        const int d4 = t & 63;

        __shared__ float  adjs1[LL];
        __shared__ float4 red[4][64];

        adjs1[t] = adj[(b * LL + i) * LL + t];
        __syncthreads();

        const int jbase = jj << 6;
        const float4* p = (const float4*)dep
                        + (((size_t)(b * LL + jbase) * LL + i) << 6) + d4;
        const size_t jstride = (size_t)LL << 6;   // 16384 float4 per j

        float4 acc = make_float4(0.f, 0.f, 0.f, 0.f);

#pragma unroll 1
        for (int js = 0; js < 64; js += 8) {
            float4 dv[8];
#pragma unroll
            for (int u = 0; u < 8; u++)
                dv[u] = __ldcs(p + (size_t)u * jstride);   // 8 LDG.128 in flight
            p += jstride * 8;
#pragma unroll
            for (int u = 0; u < 8; u++) {
                const float a = adjs1[jbase + js + u];
                acc.x += a * dv[u].x;
                acc.y += a * dv[u].y;
                acc.z += a * dv[u].z;
                acc.w += a * dv[u].w;
            }
        }

        red[jj][d4] = acc;
        __syncthreads();
        if (t < 64) {
            float4 r0 = red[0][t], r1 = red[1][t], r2 = red[2][t], r3 = red[3][t];
            float4 s;
            s.x = (r0.x + r1.x) + (r2.x + r3.x);
            s.y = (r0.y + r1.y) + (r2.y + r3.y);
            s.z = (r0.z + r1.z) + (r2.z + r3.z);
            s.w = (r0.w + r1.w) + (r2.w + r3.w);
            ((float4*)g_Sdep)[((b * LL + i) << 6) + t] = s;
        }
    }
}

// ---------------------------------------------------------------------------
// k_out: out[row,o] = sum_d (S0+Sdep)[row,d] * Wt[d,o] + A[row]*bias[o]
// Tile: 16 rows x 128 cols. grid = (1024/16) * (256/128) = 128 blocks.
// Thread: c4 = nt*32 + (t&31) float4-col; rg = t>>5 owns local rows 2rg, 2rg+1.
// Inner loop unrolled by 8 -> 8 independent LDG.128 on the Wt stream (MLP=8).
// ---------------------------------------------------------------------------
__global__ void __launch_bounds__(256) k_out(const float* __restrict__ bias,
                                             float* __restrict__ out) {
    const int bx  = blockIdx.x;
    const int mt  = bx >> 1;
    const int nt  = bx & 1;
    const int row0 = mt * 16;
    const int t   = threadIdx.x;
    const int c4  = nt * 32 + (t & 31);
    const int rg  = t >> 5;

    __shared__ float Ssm[16][DD];
    __shared__ float Asm[16];

    // stage S = S0 + Sdep for 16 rows (1024 float4, 4 per thread)
    {
        const float4* S0g = (const float4*)(g_S0   + (size_t)row0 * DD);
        const float4* Sdg = (const float4*)(g_Sdep + (size_t)row0 * DD);
        float4* Ss4 = (float4*)&Ssm[0][0];
#pragma unroll
        for (int k = 0; k < 4; k++) {
            const int idx = t + 256 * k;
            float4 a = S0g[idx];
            float4 c = Sdg[idx];
            a.x += c.x; a.y += c.y; a.z += c.z; a.w += c.w;
            Ss4[idx] = a;
        }
        if (t < 16) Asm[t] = g_A[row0 + t];
    }
    __syncthreads();

    const int r0 = rg * 2, r1 = rg * 2 + 1;
    float4 acc0 = make_float4(0.f, 0.f, 0.f, 0.f);
    float4 acc1 = make_float4(0.f, 0.f, 0.f, 0.f);
    const float4* Wt4 = (const float4*)g_Wt + c4;

#pragma unroll 1
    for (int d = 0; d < DD; d += 8) {
        float4 wv[8];
#pragma unroll
        for (int u = 0; u < 8; u++) wv[u] = Wt4[(d + u) << 6];
        float s0[8], s1[8];
#pragma unroll
        for (int u = 0; u < 8; u++) { s0[u] = Ssm[r0][d + u]; s1[u] = Ssm[r1][d + u]; }
#pragma unroll
        for (int u = 0; u < 8; u++) {
            acc0.x += s0[u] * wv[u].x;  acc0.y += s0[u] * wv[u].y;
            acc0.z += s0[u] * wv[u].z;  acc0.w += s0[u] * wv[u].w;
            acc1.x += s1[u] * wv[u].x;  acc1.y += s1[u] * wv[u].y;
            acc1.z += s1[u] * wv[u].z;  acc1.w += s1[u] * wv[u].w;
        }
    }

    const float4 bi = ((const float4*)bias)[c4];
    const float a0 = Asm[r0], a1 = Asm[r1];
    acc0.x += a0 * bi.x;  acc0.y += a0 * bi.y;
    acc0.z += a0 * bi.z;  acc0.w += a0 * bi.w;
    acc1.x += a1 * bi.x;  acc1.y += a1 * bi.y;
    acc1.z += a1 * bi.z;  acc1.w += a1 * bi.w;

    ((float4*)(out + (size_t)(row0 + r0) * DD))[c4] = acc0;
    ((float4*)(out + (size_t)(row0 + r1) * DD))[c4] = acc1;
}

// ---------------------------------------------------------------------------
extern "C" void kernel_launch(void* const* d_in, const int* in_sizes, int n_in,
                              void* d_out, int out_size) {
    const float* text = (const float*)d_in[0];  // [4,256,256]
    const float* adj  = (const float*)d_in[1];  // [4,256,256]
    const float* dep  = (const float*)d_in[2];  // [4,256,256,256]
    const float* W    = (const float*)d_in[3];  // [256,256]
    const float* bias = (const float*)d_in[4];  // [256]
    float* out = (float*)d_out;                 // [4,256,256]

    k_fused<<<192 + BB * LL, 256>>>(text, adj, dep, W);
    k_out<<<128, 256>>>(bias, out);
}

// round 4
// speedup vs baseline: 1.5777x; 1.0991x over previous
#include <cuda_runtime.h>

#define BB 4
#define LL 256
#define DD 256

// scratch (allocation-free contract: __device__ globals)
__device__ float g_Sdep[BB * LL * DD];  // 1 MB : sum_j adj * dep
__device__ float g_S0[BB * LL * DD];    // 1 MB : adj @ text
__device__ float g_A[BB * LL];          // row sums of adj
__device__ float g_Wt[DD * DD];         // W transposed: Wt[d*256 + o]

// ---------------------------------------------------------------------------
// k_fused: one grid, three block roles.
//   bx in [0,128)    : S0[row,d] = sum_j adj[row,j]*text[b,j,d]; A[row]
//   bx in [128,192)  : W transpose -> g_Wt
//   bx in [192,1216) : Sdep[b,i,d] = sum_j adj[b,i,j]*dep[b,j,i,d]  (DRAM stream)
// GEMM/transpose blocks are first so they schedule in wave 1 and finish early;
// their L2/FMA work hides entirely under the DRAM-bound dep stream.
// ---------------------------------------------------------------------------
__global__ void __launch_bounds__(256) k_fused(const float* __restrict__ text,
                                               const float* __restrict__ adj,
                                               const float* __restrict__ dep,
                                               const float* __restrict__ W) {
    const int bx = blockIdx.x;
    const int t  = threadIdx.x;

    if (bx < 128) {
        // ---- S0 = adj @ text (8 rows per block), plus A row sums ----
        __shared__ float adjs[8][LL];
        const int row0 = bx * 8;            // global row = b*256 + i
        const int b    = row0 >> 8;

        const float* adjg = adj + (size_t)row0 * LL;
#pragma unroll
        for (int r = 0; r < 8; r++) adjs[r][t] = adjg[r * LL + t];
        __syncthreads();

        {   // A row sums: warp w reduces adjs[w]
            const int warp = t >> 5, lane = t & 31;
            float s = 0.f;
#pragma unroll
            for (int k = 0; k < 8; k++) s += adjs[warp][lane + 32 * k];
#pragma unroll
            for (int off = 16; off; off >>= 1)
                s += __shfl_xor_sync(0xffffffffu, s, off);
            if (lane == 0) g_A[row0 + warp] = s;
        }

        const int o4 = t & 63;
        const int rg = t >> 6;
        const int r0 = rg * 2, r1 = r0 + 1;

        const float4* text4 = (const float4*)text + ((size_t)b * LL << 6) + o4;
        float4 acc0 = make_float4(0.f, 0.f, 0.f, 0.f);
        float4 acc1 = make_float4(0.f, 0.f, 0.f, 0.f);

#pragma unroll 1
        for (int j = 0; j < LL; j += 4) {
            float4 tv[4];
#pragma unroll
            for (int u = 0; u < 4; u++) tv[u] = text4[(j + u) << 6];
#pragma unroll
            for (int u = 0; u < 4; u++) {
                const float a0 = adjs[r0][j + u];
                const float a1 = adjs[r1][j + u];
                acc0.x += a0 * tv[u].x;  acc0.y += a0 * tv[u].y;
                acc0.z += a0 * tv[u].z;  acc0.w += a0 * tv[u].w;
                acc1.x += a1 * tv[u].x;  acc1.y += a1 * tv[u].y;
                acc1.z += a1 * tv[u].z;  acc1.w += a1 * tv[u].w;
            }
        }
        ((float4*)g_S0)[((row0 + r0) << 6) + o4] = acc0;
        ((float4*)g_S0)[((row0 + r1) << 6) + o4] = acc1;
        return;
    }

    if (bx < 192) {
        // ---- W transpose: 64 blocks of 32x32 tiles ----
        __shared__ float tile[32][33];
        const int bb = bx - 128;
        const int d0 = (bb & 7) * 32, o0 = (bb >> 3) * 32;
        const int tx = t & 31, ty = t >> 5;   // (32, 8)
#pragma unroll
        for (int k = 0; k < 32; k += 8)
            tile[ty + k][tx] = W[(o0 + ty + k) * DD + (d0 + tx)];
        __syncthreads();
#pragma unroll
        for (int k = 0; k < 32; k += 8)
            g_Wt[(d0 + ty + k) * DD + (o0 + tx)] = tile[tx][ty + k];
        return;
    }

    // ---- dep stream: one (b,i) per block ----
    {
        const int id = bx - 192;
        const int b  = id >> 8;
        const int i  = id & 255;
        const int jj = t >> 6;
        const int d4 = t & 63;

        __shared__ float  adjs1[LL];
        __shared__ float4 red[4][64];

        adjs1[t] = adj[(b * LL + i) * LL + t];
        __syncthreads();

        const int jbase = jj << 6;
        const float4* p = (const float4*)dep
                        + (((size_t)(b * LL + jbase) * LL + i) << 6) + d4;
        const size_t jstride = (size_t)LL << 6;   // 16384 float4 per j

        float4 acc = make_float4(0.f, 0.f, 0.f, 0.f);

#pragma unroll 1
        for (int js = 0; js < 64; js += 8) {
            float4 dv[8];
#pragma unroll
            for (int u = 0; u < 8; u++)
                dv[u] = __ldcs(p + (size_t)u * jstride);   // 8 LDG.128 in flight
            p += jstride * 8;
#pragma unroll
            for (int u = 0; u < 8; u++) {
                const float a = adjs1[jbase + js + u];
                acc.x += a * dv[u].x;
                acc.y += a * dv[u].y;
                acc.z += a * dv[u].z;
                acc.w += a * dv[u].w;
            }
        }

        red[jj][d4] = acc;
        __syncthreads();
        if (t < 64) {
            float4 r0 = red[0][t], r1 = red[1][t], r2 = red[2][t], r3 = red[3][t];
            float4 s;
            s.x = (r0.x + r1.x) + (r2.x + r3.x);
            s.y = (r0.y + r1.y) + (r2.y + r3.y);
            s.z = (r0.z + r1.z) + (r2.z + r3.z);
            s.w = (r0.w + r1.w) + (r2.w + r3.w);
            ((float4*)g_Sdep)[((b * LL + i) << 6) + t] = s;
        }
    }
}

// ---------------------------------------------------------------------------
// k_out v3: out[row,o] = sum_d (S0+Sdep)[row,d]*Wt[d,o] + A[row]*bias[o]
// Tile: 8 rows x 128 cols -> grid = (1024/8)*(256/128) = 256 blocks.
// Thread owns ONE float4 output: r = t>>5 (local row), c4 = t&31 (float4 col).
// Wt is staged through smem in 32-d chunks, DOUBLE-BUFFERED: next chunk's
// LDGs are issued while computing the current chunk from smem, so L2 latency
// is hidden instead of exposed on the critical path.
// ---------------------------------------------------------------------------
__global__ void __launch_bounds__(256) k_out(const float* __restrict__ bias,
                                             float* __restrict__ out) {
    const int bx   = blockIdx.x;
    const int mt   = bx >> 1;
    const int nt   = bx & 1;
    const int row0 = mt * 8;
    const int t    = threadIdx.x;
    const int r    = t >> 5;      // local row 0..7
    const int c4   = t & 31;      // float4 col within 128-col half

    __shared__ float  Ssm[8][DD];       // 8 KB
    __shared__ float  Asm[8];
    __shared__ float4 Wts[2][32][32];   // 2 x 16 KB double buffer

    // stage S = S0 + Sdep for the 8 rows (512 float4, 2 per thread)
    {
        const float4* S0g = (const float4*)(g_S0   + (size_t)row0 * DD);
        const float4* Sdg = (const float4*)(g_Sdep + (size_t)row0 * DD);
        float4* Ss4 = (float4*)&Ssm[0][0];
#pragma unroll
        for (int k = 0; k < 2; k++) {
            const int idx = t + 256 * k;
            float4 a = S0g[idx];
            float4 c = Sdg[idx];
            a.x += c.x; a.y += c.y; a.z += c.z; a.w += c.w;
            Ss4[idx] = a;
        }
        if (t < 8) Asm[t] = g_A[row0 + t];
    }

    // Wt pointer for this block's column half; chunk rows d = dc + r + 8*k2
    const float4* Wtg = (const float4*)g_Wt + nt * 32 + c4;

    // prefetch chunk 0 (d = 0..31): 4 independent LDG.128
    float4 pre[4];
#pragma unroll
    for (int k2 = 0; k2 < 4; k2++)
        pre[k2] = Wtg[(r + 8 * k2) << 6];

    float4 acc = make_float4(0.f, 0.f, 0.f, 0.f);

#pragma unroll 1
    for (int ch = 0; ch < 8; ch++) {
        const int buf = ch & 1;
        // commit prefetched chunk to smem
#pragma unroll
        for (int k2 = 0; k2 < 4; k2++)
            Wts[buf][r + 8 * k2][c4] = pre[k2];
        __syncthreads();

        // issue next chunk's loads (overlap with compute below)
        if (ch < 7) {
            const int dbase = (ch + 1) * 32;
#pragma unroll
            for (int k2 = 0; k2 < 4; k2++)
                pre[k2] = Wtg[(dbase + r + 8 * k2) << 6];
        }

        // compute this chunk from smem
        const int dc = ch * 32;
#pragma unroll
        for (int dq = 0; dq < 8; dq++) {
            const float4 s4 = *(const float4*)&Ssm[r][dc + dq * 4];  // broadcast
            const float4 w0 = Wts[buf][dq * 4 + 0][c4];
            const float4 w1 = Wts[buf][dq * 4 + 1][c4];
            const float4 w2 = Wts[buf][dq * 4 + 2][c4];
            const float4 w3 = Wts[buf][dq * 4 + 3][c4];
            acc.x += s4.x * w0.x;  acc.y += s4.x * w0.y;
            acc.z += s4.x * w0.z;  acc.w += s4.x * w0.w;
            acc.x += s4.y * w1.x;  acc.y += s4.y * w1.y;
            acc.z += s4.y * w1.z;  acc.w += s4.y * w1.w;
            acc.x += s4.z * w2.x;  acc.y += s4.z * w2.y;
            acc.z += s4.z * w2.z;  acc.w += s4.z * w2.w;
            acc.x += s4.w * w3.x;  acc.y += s4.w * w3.y;
            acc.z += s4.w * w3.z;  acc.w += s4.w * w3.w;
        }
        __syncthreads();
    }

    const float4 bi = ((const float4*)bias)[nt * 32 + c4];
    const float  a0 = Asm[r];
    acc.x += a0 * bi.x;  acc.y += a0 * bi.y;
    acc.z += a0 * bi.z;  acc.w += a0 * bi.w;

    ((float4*)(out + (size_t)(row0 + r) * DD))[nt * 32 + c4] = acc;
}

// ---------------------------------------------------------------------------
extern "C" void kernel_launch(void* const* d_in, const int* in_sizes, int n_in,
                              void* d_out, int out_size) {
    const float* text = (const float*)d_in[0];  // [4,256,256]
    const float* adj  = (const float*)d_in[1];  // [4,256,256]
    const float* dep  = (const float*)d_in[2];  // [4,256,256,256]
    const float* W    = (const float*)d_in[3];  // [256,256]
    const float* bias = (const float*)d_in[4];  // [256]
    float* out = (float*)d_out;                 // [4,256,256]

    k_fused<<<192 + BB * LL, 256>>>(text, adj, dep, W);
    k_out<<<256, 256>>>(bias, out);
}

// round 5
// speedup vs baseline: 1.6497x; 1.0456x over previous
#include <cuda_runtime.h>

#define BB 4
#define LL 256
#define DD 256

// scratch (allocation-free contract: __device__ globals)
__device__ float g_Sdep[BB * LL * DD];  // 1 MB : sum_j adj * dep
__device__ float g_S0[BB * LL * DD];    // 1 MB : adj @ text
__device__ float g_A[BB * LL];          // row sums of adj
__device__ float g_Wt[DD * DD];         // W transposed: Wt[d*256 + o]

// ---------------------------------------------------------------------------
// k_fused: one grid, three block roles.
//   bx in [0,128)    : S0[row,d] = sum_j adj[row,j]*text[b,j,d]; A[row]
//   bx in [128,192)  : W transpose -> g_Wt
//   bx in [192,1216) : Sdep[b,i,d] = sum_j adj[b,i,j]*dep[b,j,i,d]  (DRAM stream)
// ---------------------------------------------------------------------------
__global__ void __launch_bounds__(256) k_fused(const float* __restrict__ text,
                                               const float* __restrict__ adj,
                                               const float* __restrict__ dep,
                                               const float* __restrict__ W) {
    const int bx = blockIdx.x;
    const int t  = threadIdx.x;

    if (bx < 128) {
        // ---- S0 = adj @ text (8 rows per block), plus A row sums ----
        __shared__ float adjs[8][LL];
        const int row0 = bx * 8;            // global row = b*256 + i
        const int b    = row0 >> 8;

        const float* adjg = adj + (size_t)row0 * LL;
#pragma unroll
        for (int r = 0; r < 8; r++) adjs[r][t] = adjg[r * LL + t];
        __syncthreads();

        {   // A row sums: warp w reduces adjs[w]
            const int warp = t >> 5, lane = t & 31;
            float s = 0.f;
#pragma unroll
            for (int k = 0; k < 8; k++) s += adjs[warp][lane + 32 * k];
#pragma unroll
            for (int off = 16; off; off >>= 1)
                s += __shfl_xor_sync(0xffffffffu, s, off);
            if (lane == 0) g_A[row0 + warp] = s;
        }

        const int o4 = t & 63;
        const int rg = t >> 6;
        const int r0 = rg * 2, r1 = r0 + 1;

        const float4* text4 = (const float4*)text + ((size_t)b * LL << 6) + o4;
        float4 acc0 = make_float4(0.f, 0.f, 0.f, 0.f);
        float4 acc1 = make_float4(0.f, 0.f, 0.f, 0.f);

#pragma unroll 1
        for (int j = 0; j < LL; j += 4) {
            float4 tv[4];
#pragma unroll
            for (int u = 0; u < 4; u++) tv[u] = text4[(j + u) << 6];
#pragma unroll
            for (int u = 0; u < 4; u++) {
                const float a0 = adjs[r0][j + u];
                const float a1 = adjs[r1][j + u];
                acc0.x += a0 * tv[u].x;  acc0.y += a0 * tv[u].y;
                acc0.z += a0 * tv[u].z;  acc0.w += a0 * tv[u].w;
                acc1.x += a1 * tv[u].x;  acc1.y += a1 * tv[u].y;
                acc1.z += a1 * tv[u].z;  acc1.w += a1 * tv[u].w;
            }
        }
        ((float4*)g_S0)[((row0 + r0) << 6) + o4] = acc0;
        ((float4*)g_S0)[((row0 + r1) << 6) + o4] = acc1;
        return;
    }

    if (bx < 192) {
        // ---- W transpose: 64 blocks of 32x32 tiles ----
        __shared__ float tile[32][33];
        const int bb = bx - 128;
        const int d0 = (bb & 7) * 32, o0 = (bb >> 3) * 32;
        const int tx = t & 31, ty = t >> 5;   // (32, 8)
#pragma unroll
        for (int k = 0; k < 32; k += 8)
            tile[ty + k][tx] = W[(o0 + ty + k) * DD + (d0 + tx)];
        __syncthreads();
#pragma unroll
        for (int k = 0; k < 32; k += 8)
            g_Wt[(d0 + ty + k) * DD + (o0 + tx)] = tile[tx][ty + k];
        return;
    }

    // ---- dep stream: one (b,i) per block ----
    {
        const int id = bx - 192;
        const int b  = id >> 8;
        const int i  = id & 255;
        const int jj = t >> 6;
        const int d4 = t & 63;

        __shared__ float  adjs1[LL];
        __shared__ float4 red[4][64];

        adjs1[t] = adj[(b * LL + i) * LL + t];
        __syncthreads();

        const int jbase = jj << 6;
        const float4* p = (const float4*)dep
                        + (((size_t)(b * LL + jbase) * LL + i) << 6) + d4;
        const size_t jstride = (size_t)LL << 6;   // 16384 float4 per j

        float4 acc = make_float4(0.f, 0.f, 0.f, 0.f);

#pragma unroll 1
        for (int js = 0; js < 64; js += 8) {
            float4 dv[8];
#pragma unroll
            for (int u = 0; u < 8; u++)
                dv[u] = __ldcs(p + (size_t)u * jstride);   // 8 LDG.128 in flight
            p += jstride * 8;
#pragma unroll
            for (int u = 0; u < 8; u++) {
                const float a = adjs1[jbase + js + u];
                acc.x += a * dv[u].x;
                acc.y += a * dv[u].y;
                acc.z += a * dv[u].z;
                acc.w += a * dv[u].w;
            }
        }

        red[jj][d4] = acc;
        __syncthreads();
        if (t < 64) {
            float4 r0 = red[0][t], r1 = red[1][t], r2 = red[2][t], r3 = red[3][t];
            float4 s;
            s.x = (r0.x + r1.x) + (r2.x + r3.x);
            s.y = (r0.y + r1.y) + (r2.y + r3.y);
            s.z = (r0.z + r1.z) + (r2.z + r3.z);
            s.w = (r0.w + r1.w) + (r2.w + r3.w);
            ((float4*)g_Sdep)[((b * LL + i) << 6) + t] = s;
        }
    }
}

// ---------------------------------------------------------------------------
// k_out v5: out[row,o] = sum_d (S0+Sdep)[row,d]*Wt[d,o] + A[row]*bias[o]
// Tile: 8 rows x 128 cols, grid 256 blocks, block = 128 threads.
// Thread owns TWO float4 outputs (rows rg*2, rg*2+1; col c4) -> each Wt value
// read from smem feeds 8 FFMA (halves crossbar load vs v3). Wt double-buffered
// through smem in 32-d chunks; s-row reads are warp-uniform broadcasts.
// ---------------------------------------------------------------------------
__global__ void __launch_bounds__(128) k_out(const float* __restrict__ bias,
                                             float* __restrict__ out) {
    const int bx   = blockIdx.x;
    const int mt   = bx >> 1;
    const int nt   = bx & 1;
    const int row0 = mt * 8;
    const int t    = threadIdx.x;
    const int c4   = t & 31;      // float4 col within the 128-col half
    const int rg   = t >> 5;      // row group 0..3 (rows 2rg, 2rg+1)

    __shared__ float  Ssm[8][DD];       // 8 KB
    __shared__ float  Asm[8];
    __shared__ float4 Wts[2][32][32];   // 2 x 16 KB double buffer

    // stage S = S0 + Sdep for the 8 rows (512 float4, 4 per thread)
    {
        const float4* S0g = (const float4*)(g_S0   + (size_t)row0 * DD);
        const float4* Sdg = (const float4*)(g_Sdep + (size_t)row0 * DD);
        float4* Ss4 = (float4*)&Ssm[0][0];
#pragma unroll
        for (int k = 0; k < 4; k++) {
            const int idx = t + 128 * k;
            float4 a = S0g[idx];
            float4 c = Sdg[idx];
            a.x += c.x; a.y += c.y; a.z += c.z; a.w += c.w;
            Ss4[idx] = a;
        }
        if (t < 8) Asm[t] = g_A[row0 + t];
    }

    // Wt pointer for this block's column half; this thread loads 8 d's/chunk:
    // d = dbase + rg*8 + k, k = 0..7  -> 8 independent LDG.128 (MLP=8)
    const float4* Wtg = (const float4*)g_Wt + nt * 32 + c4;

    float4 pre[8];
#pragma unroll
    for (int k = 0; k < 8; k++)
        pre[k] = Wtg[(rg * 8 + k) << 6];

    float4 acc0 = make_float4(0.f, 0.f, 0.f, 0.f);
    float4 acc1 = make_float4(0.f, 0.f, 0.f, 0.f);
    const int r0 = rg * 2, r1 = r0 + 1;

#pragma unroll 1
    for (int ch = 0; ch < 8; ch++) {
        const int buf = ch & 1;
        // commit prefetched chunk to smem
#pragma unroll
        for (int k = 0; k < 8; k++)
            Wts[buf][rg * 8 + k][c4] = pre[k];
        __syncthreads();

        // issue next chunk's loads (overlap with compute below)
        if (ch < 7) {
            const int dbase = (ch + 1) * 32;
#pragma unroll
            for (int k = 0; k < 8; k++)
                pre[k] = Wtg[(dbase + rg * 8 + k) << 6];
        }

        // compute this chunk from smem: 2 rows x 4 cols x 32 d = 256 FFMA
        const int dc = ch * 32;
#pragma unroll
        for (int dq = 0; dq < 8; dq++) {
            const float4 s0 = *(const float4*)&Ssm[r0][dc + dq * 4];  // bcast
            const float4 s1 = *(const float4*)&Ssm[r1][dc + dq * 4];  // bcast
            const float4 w0 = Wts[buf][dq * 4 + 0][c4];
            const float4 w1 = Wts[buf][dq * 4 + 1][c4];
            const float4 w2 = Wts[buf][dq * 4 + 2][c4];
            const float4 w3 = Wts[buf][dq * 4 + 3][c4];
            acc0.x += s0.x * w0.x;  acc0.y += s0.x * w0.y;
            acc0.z += s0.x * w0.z;  acc0.w += s0.x * w0.w;
            acc1.x += s1.x * w0.x;  acc1.y += s1.x * w0.y;
            acc1.z += s1.x * w0.z;  acc1.w += s1.x * w0.w;
            acc0.x += s0.y * w1.x;  acc0.y += s0.y * w1.y;
            acc0.z += s0.y * w1.z;  acc0.w += s0.y * w1.w;
            acc1.x += s1.y * w1.x;  acc1.y += s1.y * w1.y;
            acc1.z += s1.y * w1.z;  acc1.w += s1.y * w1.w;
            acc0.x += s0.z * w2.x;  acc0.y += s0.z * w2.y;
            acc0.z += s0.z * w2.z;  acc0.w += s0.z * w2.w;
            acc1.x += s1.z * w2.x;  acc1.y += s1.z * w2.y;
            acc1.z += s1.z * w2.z;  acc1.w += s1.z * w2.w;
            acc0.x += s0.w * w3.x;  acc0.y += s0.w * w3.y;
            acc0.z += s0.w * w3.z;  acc0.w += s0.w * w3.w;
            acc1.x += s1.w * w3.x;  acc1.y += s1.w * w3.y;
            acc1.z += s1.w * w3.z;  acc1.w += s1.w * w3.w;
        }
        __syncthreads();
    }

    const float4 bi = ((const float4*)bias)[nt * 32 + c4];
    const float  a0 = Asm[r0];
    const float  a1 = Asm[r1];
    acc0.x += a0 * bi.x;  acc0.y += a0 * bi.y;
    acc0.z += a0 * bi.z;  acc0.w += a0 * bi.w;
    acc1.x += a1 * bi.x;  acc1.y += a1 * bi.y;
    acc1.z += a1 * bi.z;  acc1.w += a1 * bi.w;

    ((float4*)(out + (size_t)(row0 + r0) * DD))[nt * 32 + c4] = acc0;
    ((float4*)(out + (size_t)(row0 + r1) * DD))[nt * 32 + c4] = acc1;
}

// ---------------------------------------------------------------------------
extern "C" void kernel_launch(void* const* d_in, const int* in_sizes, int n_in,
                              void* d_out, int out_size) {
    const float* text = (const float*)d_in[0];  // [4,256,256]
    const float* adj  = (const float*)d_in[1];  // [4,256,256]
    const float* dep  = (const float*)d_in[2];  // [4,256,256,256]
    const float* W    = (const float*)d_in[3];  // [256,256]
    const float* bias = (const float*)d_in[4];  // [256]
    float* out = (float*)d_out;                 // [4,256,256]

    k_fused<<<192 + BB * LL, 256>>>(text, adj, dep, W);
    k_out<<<256, 128>>>(bias, out);
}

// round 6
// speedup vs baseline: 1.7355x; 1.0520x over previous
#include <cuda_runtime.h>

#define BB 4
#define LL 256
#define DD 256

// scratch (allocation-free contract: __device__ globals)
__device__ float g_Sdep[BB * LL * DD];  // 1 MB : sum_j adj * dep
__device__ float g_S0[BB * LL * DD];    // 1 MB : adj @ text
__device__ float g_A[BB * LL];          // row sums of adj
__device__ float g_Wt[DD * DD];         // W transposed: Wt[d*256 + o]

// ---------------------------------------------------------------------------
// k_fused: grid = 1184 = 148 SMs x 8 CTAs  (exactly one resident wave)
//   bx in [0,128)    : S0[row,d] = sum_j adj[row,j]*text[b,j,d]; A[row]
//   bx in [128,160)  : W transpose -> g_Wt (2 tiles per block)
//   bx in [160,1184) : Sdep[b,i,d] = sum_j adj[b,i,j]*dep[b,j,i,d] (DRAM stream)
// ---------------------------------------------------------------------------
__global__ void __launch_bounds__(256) k_fused(const float* __restrict__ text,
                                               const float* __restrict__ adj,
                                               const float* __restrict__ dep,
                                               const float* __restrict__ W) {
    const int bx = blockIdx.x;
    const int t  = threadIdx.x;

    if (bx < 128) {
        // ---- S0 = adj @ text (8 rows per block), plus A row sums ----
        __shared__ float adjs[8][LL];
        const int row0 = bx * 8;            // global row = b*256 + i
        const int b    = row0 >> 8;

        const float* adjg = adj + (size_t)row0 * LL;
#pragma unroll
        for (int r = 0; r < 8; r++) adjs[r][t] = adjg[r * LL + t];
        __syncthreads();

        {   // A row sums: warp w reduces adjs[w]
            const int warp = t >> 5, lane = t & 31;
            float s = 0.f;
#pragma unroll
            for (int k = 0; k < 8; k++) s += adjs[warp][lane + 32 * k];
#pragma unroll
            for (int off = 16; off; off >>= 1)
                s += __shfl_xor_sync(0xffffffffu, s, off);
            if (lane == 0) g_A[row0 + warp] = s;
        }

        const int o4 = t & 63;
        const int rg = t >> 6;
        const int r0 = rg * 2, r1 = r0 + 1;

        const float4* text4 = (const float4*)text + ((size_t)b * LL << 6) + o4;
        float4 acc0 = make_float4(0.f, 0.f, 0.f, 0.f);
        float4 acc1 = make_float4(0.f, 0.f, 0.f, 0.f);

#pragma unroll 1
        for (int j = 0; j < LL; j += 4) {
            float4 tv[4];
#pragma unroll
            for (int u = 0; u < 4; u++) tv[u] = text4[(j + u) << 6];
#pragma unroll
            for (int u = 0; u < 4; u++) {
                const float a0 = adjs[r0][j + u];
                const float a1 = adjs[r1][j + u];
                acc0.x += a0 * tv[u].x;  acc0.y += a0 * tv[u].y;
                acc0.z += a0 * tv[u].z;  acc0.w += a0 * tv[u].w;
                acc1.x += a1 * tv[u].x;  acc1.y += a1 * tv[u].y;
                acc1.z += a1 * tv[u].z;  acc1.w += a1 * tv[u].w;
            }
        }
        ((float4*)g_S0)[((row0 + r0) << 6) + o4] = acc0;
        ((float4*)g_S0)[((row0 + r1) << 6) + o4] = acc1;
        return;
    }

    if (bx < 160) {
        // ---- W transpose: 32 blocks x 2 tiles of 32x32 ----
        __shared__ float tile[32][33];
        const int tx = t & 31, ty = t >> 5;   // (32, 8)
#pragma unroll 1
        for (int pass = 0; pass < 2; pass++) {
            const int bb = (bx - 128) + pass * 32;
            const int d0 = (bb & 7) * 32, o0 = (bb >> 3) * 32;
#pragma unroll
            for (int k = 0; k < 32; k += 8)
                tile[ty + k][tx] = W[(o0 + ty + k) * DD + (d0 + tx)];
            __syncthreads();
#pragma unroll
            for (int k = 0; k < 32; k += 8)
                g_Wt[(d0 + ty + k) * DD + (o0 + tx)] = tile[tx][ty + k];
            __syncthreads();
        }
        return;
    }

    // ---- dep stream: one (b,i) per block ----
    {
        const int id = bx - 160;
        const int b  = id >> 8;
        const int i  = id & 255;
        const int jj = t >> 6;
        const int d4 = t & 63;

        __shared__ float  adjs1[LL];
        __shared__ float4 red[4][64];

        adjs1[t] = adj[(b * LL + i) * LL + t];
        __syncthreads();

        const int jbase = jj << 6;
        const float4* p = (const float4*)dep
                        + (((size_t)(b * LL + jbase) * LL + i) << 6) + d4;
        const size_t jstride = (size_t)LL << 6;   // 16384 float4 per j

        float4 acc = make_float4(0.f, 0.f, 0.f, 0.f);

#pragma unroll 1
        for (int js = 0; js < 64; js += 8) {
            float4 dv[8];
#pragma unroll
            for (int u = 0; u < 8; u++)
                dv[u] = __ldcs(p + (size_t)u * jstride);   // 8 LDG.128 in flight
            p += jstride * 8;
#pragma unroll
            for (int u = 0; u < 8; u++) {
                const float a = adjs1[jbase + js + u];
                acc.x += a * dv[u].x;
                acc.y += a * dv[u].y;
                acc.z += a * dv[u].z;
                acc.w += a * dv[u].w;
            }
        }

        red[jj][d4] = acc;
        __syncthreads();
        if (t < 64) {
            float4 r0 = red[0][t], r1 = red[1][t], r2 = red[2][t], r3 = red[3][t];
            float4 s;
            s.x = (r0.x + r1.x) + (r2.x + r3.x);
            s.y = (r0.y + r1.y) + (r2.y + r3.y);
            s.z = (r0.z + r1.z) + (r2.z + r3.z);
            s.w = (r0.w + r1.w) + (r2.w + r3.w);
            ((float4*)g_Sdep)[((b * LL + i) << 6) + t] = s;
        }
    }
}

// ---------------------------------------------------------------------------
// k_out v6: out[row,o] = sum_d (S0+Sdep)[row,d]*Wt[d,o] + A[row]*bias[o]
// Tile: 16 rows x 128 cols, grid 128 blocks, block = 128 threads.
// Thread owns FOUR rows x one float4 col (4 float4 outputs) -> each Wt value
// read from smem feeds 16 FFMA (halves crossbar vs v5: ~2us floor, balanced
// with ~1us FMA). Wt double-buffered through smem in 32-d chunks; S-row reads
// are warp-uniform broadcasts (warp = one row group).
// ---------------------------------------------------------------------------
__global__ void __launch_bounds__(128) k_out(const float* __restrict__ bias,
                                             float* __restrict__ out) {
    const int bx   = blockIdx.x;
    const int mt   = bx >> 1;
    const int nt   = bx & 1;
    const int row0 = mt * 16;
    const int t    = threadIdx.x;
    const int c4   = t & 31;      // float4 col within the 128-col half
    const int rg   = t >> 5;      // row group 0..3 -> rows rg*4 .. rg*4+3

    __shared__ float  Ssm[16][DD];      // 16 KB
    __shared__ float  Asm[16];
    __shared__ float4 Wts[2][32][32];   // 2 x 16 KB double buffer

    // stage S = S0 + Sdep for the 16 rows (1024 float4, 8 per thread)
    {
        const float4* S0g = (const float4*)(g_S0   + (size_t)row0 * DD);
        const float4* Sdg = (const float4*)(g_Sdep + (size_t)row0 * DD);
        float4* Ss4 = (float4*)&Ssm[0][0];
#pragma unroll
        for (int k = 0; k < 8; k++) {
            const int idx = t + 128 * k;
            float4 a = S0g[idx];
            float4 c = Sdg[idx];
            a.x += c.x; a.y += c.y; a.z += c.z; a.w += c.w;
            Ss4[idx] = a;
        }
        if (t < 16) Asm[t] = g_A[row0 + t];
    }

    // Wt global pointer for this block's column half; per chunk this thread
    // loads 8 d's: d = dbase + rg*8 + k  -> 8 independent LDG.128 (MLP=8)
    const float4* Wtg = (const float4*)g_Wt + nt * 32 + c4;

    float4 pre[8];
#pragma unroll
    for (int k = 0; k < 8; k++)
        pre[k] = Wtg[(rg * 8 + k) << 6];

    float4 acc[4];
#pragma unroll
    for (int j = 0; j < 4; j++) acc[j] = make_float4(0.f, 0.f, 0.f, 0.f);
    const int rbase = rg * 4;

#pragma unroll 1
    for (int ch = 0; ch < 8; ch++) {
        const int buf = ch & 1;
        // commit prefetched chunk to smem (conflict-free: row fixed, c4 0..31)
#pragma unroll
        for (int k = 0; k < 8; k++)
            Wts[buf][rg * 8 + k][c4] = pre[k];
        __syncthreads();

        // issue next chunk's loads (overlap with compute below)
        if (ch < 7) {
            const int dbase = (ch + 1) * 32;
#pragma unroll
            for (int k = 0; k < 8; k++)
                pre[k] = Wtg[(dbase + rg * 8 + k) << 6];
        }

        // compute this chunk: 4 rows x 4 cols x 32 d = 512 FFMA / thread
        const int dc = ch * 32;
#pragma unroll
        for (int dq = 0; dq < 8; dq++) {
            const float4 w0 = Wts[buf][dq * 4 + 0][c4];
            const float4 w1 = Wts[buf][dq * 4 + 1][c4];
            const float4 w2 = Wts[buf][dq * 4 + 2][c4];
            const float4 w3 = Wts[buf][dq * 4 + 3][c4];
#pragma unroll
            for (int j = 0; j < 4; j++) {
                const float4 s = *(const float4*)&Ssm[rbase + j][dc + dq * 4]; // bcast
                acc[j].x += s.x * w0.x;  acc[j].y += s.x * w0.y;
                acc[j].z += s.x * w0.z;  acc[j].w += s.x * w0.w;
                acc[j].x += s.y * w1.x;  acc[j].y += s.y * w1.y;
                acc[j].z += s.y * w1.z;  acc[j].w += s.y * w1.w;
                acc[j].x += s.z * w2.x;  acc[j].y += s.z * w2.y;
                acc[j].z += s.z * w2.z;  acc[j].w += s.z * w2.w;
                acc[j].x += s.w * w3.x;  acc[j].y += s.w * w3.y;
                acc[j].z += s.w * w3.z;  acc[j].w += s.w * w3.w;
            }
        }
        __syncthreads();
    }

    const float4 bi = ((const float4*)bias)[nt * 32 + c4];
#pragma unroll
    for (int j = 0; j < 4; j++) {
        const float a = Asm[rbase + j];
        acc[j].x += a * bi.x;  acc[j].y += a * bi.y;
        acc[j].z += a * bi.z;  acc[j].w += a * bi.w;
        ((float4*)(out + (size_t)(row0 + rbase + j) * DD))[nt * 32 + c4] = acc[j];
    }
}

// ---------------------------------------------------------------------------
extern "C" void kernel_launch(void* const* d_in, const int* in_sizes, int n_in,
                              void* d_out, int out_size) {
    const float* text = (const float*)d_in[0];  // [4,256,256]
    const float* adj  = (const float*)d_in[1];  // [4,256,256]
    const float* dep  = (const float*)d_in[2];  // [4,256,256,256]
    const float* W    = (const float*)d_in[3];  // [256,256]
    const float* bias = (const float*)d_in[4];  // [256]
    float* out = (float*)d_out;                 // [4,256,256]

    k_fused<<<160 + BB * LL, 256>>>(text, adj, dep, W);   // 1184 = 148 x 8
    k_out<<<128, 128>>>(bias, out);
}